// round 1
// baseline (speedup 1.0000x reference)
#include <cuda_runtime.h>
#include <cuda_bf16.h>
#include <cstdint>

#define N_TOK   2048
#define BATCH   64
#define SDIM    512
#define EDIM    512
#define NSPLIT  8
#define CHUNK   (N_TOK / NSPLIT)   // 256
#define NT      8                  // rows per tile
#define THREADS 128                // each thread owns one float4 of E

// Scratch: partial softmax stats + weighted accumulators per (split, b).
__device__ float g_m[NSPLIT * BATCH];
__device__ float g_l[NSPLIT * BATCH];
__device__ float g_acc[NSPLIT * BATCH * EDIM];   // 1 MiB

// ---------------------------------------------------------------------------
// Pass 1: per (split, b) chunk — single read of embeddings, online softmax.
// grid = (NSPLIT, BATCH), block = 128.
// ---------------------------------------------------------------------------
__global__ void __launch_bounds__(THREADS)
attn_pass1(const float* __restrict__ emb, const float* __restrict__ W)
{
    const int split = blockIdx.x;
    const int b     = blockIdx.y;
    const int t     = threadIdx.x;          // 0..127
    const int warp  = t >> 5;
    const int lane  = t & 31;

    __shared__ float sh_red[4][NT];
    __shared__ float sh_logit[NT];
    __shared__ float sh_p[NT];

    // W_e slice for this thread's 4 E-dims (W is (SD+ED,1) contiguous).
    const float4 we = reinterpret_cast<const float4*>(W + SDIM)[t];

    float4 acc = make_float4(0.f, 0.f, 0.f, 0.f);
    float  m   = -1e30f;
    float  l   = 0.f;

    const int n0 = split * CHUNK;
    // emb[n,b,e] at n*B*ED + b*ED + e ; as float4: stride per n = B*ED/4 = 8192
    const float4* e4 = reinterpret_cast<const float4*>(emb)
                     + (size_t)b * (EDIM / 4) + t;
    const size_t n_stride = (size_t)BATCH * (EDIM / 4);

    for (int nn = 0; nn < CHUNK; nn += NT) {
        // --- load NT rows (streaming: read-once data) ---
        float4 v[NT];
        #pragma unroll
        for (int i = 0; i < NT; i++)
            v[i] = __ldcs(e4 + (size_t)(n0 + nn + i) * n_stride);

        // --- partial dots with W_e ---
        float pd[NT];
        #pragma unroll
        for (int i = 0; i < NT; i++)
            pd[i] = v[i].x * we.x + v[i].y * we.y + v[i].z * we.z + v[i].w * we.w;

        // --- warp reduce all NT dots ---
        #pragma unroll
        for (int off = 16; off; off >>= 1) {
            #pragma unroll
            for (int i = 0; i < NT; i++)
                pd[i] += __shfl_xor_sync(0xffffffffu, pd[i], off);
        }
        if (lane == 0) {
            #pragma unroll
            for (int i = 0; i < NT; i++)
                sh_red[warp][i] = pd[i];
        }
        __syncthreads();

        // --- finalize NT logits (threads 0..NT-1) ---
        if (t < NT)
            sh_logit[t] = sh_red[0][t] + sh_red[1][t] + sh_red[2][t] + sh_red[3][t];
        __syncthreads();

        // --- online softmax update (all threads compute identical stats) ---
        float tm = sh_logit[0];
        #pragma unroll
        for (int i = 1; i < NT; i++) tm = fmaxf(tm, sh_logit[i]);
        const float m_new = fmaxf(m, tm);
        const float scale = __expf(m - m_new);
        if (t < NT)
            sh_p[t] = __expf(sh_logit[t] - m_new);   // exp computed ONCE per n
        __syncthreads();

        m = m_new;
        l *= scale;
        acc.x *= scale; acc.y *= scale; acc.z *= scale; acc.w *= scale;
        #pragma unroll
        for (int i = 0; i < NT; i++) {
            const float p = sh_p[i];
            l     += p;
            acc.x += p * v[i].x;
            acc.y += p * v[i].y;
            acc.z += p * v[i].z;
            acc.w += p * v[i].w;
        }
    }

    const int sb = split * BATCH + b;
    if (t == 0) { g_m[sb] = m; g_l[sb] = l; }
    reinterpret_cast<float4*>(g_acc)[(size_t)sb * (EDIM / 4) + t] = acc;
}

// ---------------------------------------------------------------------------
// Pass 2: merge NSPLIT partials per b. grid = BATCH, block = 128.
// ---------------------------------------------------------------------------
__global__ void __launch_bounds__(THREADS)
attn_pass2(float* __restrict__ out)
{
    const int b = blockIdx.x;
    const int t = threadIdx.x;

    float M = -1e30f;
    #pragma unroll
    for (int s = 0; s < NSPLIT; s++)
        M = fmaxf(M, g_m[s * BATCH + b]);

    float w[NSPLIT];
    float L = 0.f;
    #pragma unroll
    for (int s = 0; s < NSPLIT; s++) {
        w[s] = __expf(g_m[s * BATCH + b] - M);
        L   += w[s] * g_l[s * BATCH + b];
    }
    const float inv = 1.0f / L;

    float4 o = make_float4(0.f, 0.f, 0.f, 0.f);
    #pragma unroll
    for (int s = 0; s < NSPLIT; s++) {
        const float4 a = reinterpret_cast<const float4*>(g_acc)
                             [(size_t)(s * BATCH + b) * (EDIM / 4) + t];
        o.x += w[s] * a.x;
        o.y += w[s] * a.y;
        o.z += w[s] * a.z;
        o.w += w[s] * a.w;
    }
    o.x *= inv; o.y *= inv; o.z *= inv; o.w *= inv;
    reinterpret_cast<float4*>(out)[(size_t)b * (EDIM / 4) + t] = o;
}

// ---------------------------------------------------------------------------
// Inputs (metadata order): 0=state_tm1 (B,SD)  1=embeddings (N,B,ED)
//                          2=W (SD+ED,1)       3=b (1,)
// state_tm1 / b / W_s are provably irrelevant: the per-b constant state_score
// cancels in softmax over n. Output: (B, ED) float32.
// ---------------------------------------------------------------------------
extern "C" void kernel_launch(void* const* d_in, const int* in_sizes, int n_in,
                              void* d_out, int out_size)
{
    const float* emb = (const float*)d_in[1];
    const float* W   = (const float*)d_in[2];
    float*       out = (float*)d_out;

    dim3 grid1(NSPLIT, BATCH);
    attn_pass1<<<grid1, THREADS>>>(emb, W);
    attn_pass2<<<BATCH, THREADS>>>(out);
}

// round 3
// speedup vs baseline: 1.1712x; 1.1712x over previous
#include <cuda_runtime.h>
#include <cuda_bf16.h>
#include <cstdint>

#define N_TOK   2048
#define BATCH   64
#define SDIM    512
#define EDIM    512
#define NSPLIT  8
#define CHUNK   (N_TOK / NSPLIT)   // 256
#define NT      8                  // rows per tile
#define NTILES  (CHUNK / NT)       // 32
#define THREADS 128                // each thread owns one float4 of E

// Scratch: partial softmax stats + weighted accumulators per (split, b).
__device__ float g_m[NSPLIT * BATCH];
__device__ float g_l[NSPLIT * BATCH];
__device__ float g_acc[NSPLIT * BATCH * EDIM];   // 1 MiB
__device__ int   g_cnt[BATCH];                   // zero-init; reset after merge

// ---------------------------------------------------------------------------
// Single fused kernel. grid = (NSPLIT, BATCH), block = 128.
// Per CTA: online-softmax over its 256-row chunk (embeddings read exactly
// once, streaming), then the LAST CTA per batch column merges all splits.
// ---------------------------------------------------------------------------
__global__ void __launch_bounds__(THREADS)
attn_fused(const float* __restrict__ emb, const float* __restrict__ W,
           float* __restrict__ out)
{
    const int split = blockIdx.x;
    const int b     = blockIdx.y;
    const int t     = threadIdx.x;          // 0..127
    const int warp  = t >> 5;
    const int lane  = t & 31;

    __shared__ float sh_red[2][4][NT];      // double-buffered cross-warp partials
    __shared__ int   sh_last;

    // W_e slice for this thread's 4 E-dims (W is (SD+ED,1) contiguous).
    const float4 we = reinterpret_cast<const float4*>(W + SDIM)[t];

    float4 acc = make_float4(0.f, 0.f, 0.f, 0.f);
    float  m   = -1e30f;
    float  l   = 0.f;

    const int n0 = split * CHUNK;
    // emb[n,b,e] at n*B*ED + b*ED + e ; float4 stride per n = B*ED/4 = 8192
    const float4* e4 = reinterpret_cast<const float4*>(emb)
                     + (size_t)n0 * (BATCH * (EDIM / 4))
                     + (size_t)b * (EDIM / 4) + t;
    const size_t n_stride = (size_t)BATCH * (EDIM / 4);

    // --- prologue: load tile 0 ---
    float4 vbuf[2][NT];
    #pragma unroll
    for (int i = 0; i < NT; i++)
        vbuf[0][i] = __ldcs(e4 + (size_t)i * n_stride);

    #pragma unroll 2
    for (int it = 0; it < NTILES; it++) {
        const int cur = it & 1;
        const int nxt = cur ^ 1;

        // partial dots for current tile
        float pd[NT];
        #pragma unroll
        for (int i = 0; i < NT; i++)
            pd[i] = vbuf[cur][i].x * we.x + vbuf[cur][i].y * we.y
                  + vbuf[cur][i].z * we.z + vbuf[cur][i].w * we.w;

        // prefetch next tile — keeps LDGs in flight through the reduction
        if (it + 1 < NTILES) {
            const float4* p = e4 + (size_t)(it + 1) * NT * n_stride;
            #pragma unroll
            for (int i = 0; i < NT; i++)
                vbuf[nxt][i] = __ldcs(p + (size_t)i * n_stride);
        }

        // warp reduce all NT dots
        #pragma unroll
        for (int off = 16; off; off >>= 1) {
            #pragma unroll
            for (int i = 0; i < NT; i++)
                pd[i] += __shfl_xor_sync(0xffffffffu, pd[i], off);
        }
        if (lane == 0) {
            #pragma unroll
            for (int i = 0; i < NT; i++)
                sh_red[cur][warp][i] = pd[i];
        }
        __syncthreads();                     // ONLY barrier this tile

        // every thread finalizes logits + softmax update redundantly
        float lg[NT];
        #pragma unroll
        for (int i = 0; i < NT; i++)
            lg[i] = sh_red[cur][0][i] + sh_red[cur][1][i]
                  + sh_red[cur][2][i] + sh_red[cur][3][i];

        float tm = lg[0];
        #pragma unroll
        for (int i = 1; i < NT; i++) tm = fmaxf(tm, lg[i]);
        const float m_new = fmaxf(m, tm);
        const float scale = __expf(m - m_new);
        m = m_new;
        l *= scale;
        acc.x *= scale; acc.y *= scale; acc.z *= scale; acc.w *= scale;
        #pragma unroll
        for (int i = 0; i < NT; i++) {
            const float p = __expf(lg[i] - m_new);
            l     += p;
            acc.x += p * vbuf[cur][i].x;
            acc.y += p * vbuf[cur][i].y;
            acc.z += p * vbuf[cur][i].z;
            acc.w += p * vbuf[cur][i].w;
        }
    }

    // --- publish partials ---
    const int sb = split * BATCH + b;
    if (t == 0) { g_m[sb] = m; g_l[sb] = l; }
    reinterpret_cast<float4*>(g_acc)[(size_t)sb * (EDIM / 4) + t] = acc;

    // --- last CTA per b merges all splits (fused pass2) ---
    __threadfence();
    if (t == 0) {
        int old = atomicAdd(&g_cnt[b], 1);
        sh_last = (old == NSPLIT - 1);
    }
    __syncthreads();
    if (!sh_last) return;
    __threadfence();   // order partial reads after observing the final count

    float M = -1e30f;
    #pragma unroll
    for (int s = 0; s < NSPLIT; s++)
        M = fmaxf(M, g_m[s * BATCH + b]);

    float w[NSPLIT];
    float L = 0.f;
    #pragma unroll
    for (int s = 0; s < NSPLIT; s++) {
        w[s] = __expf(g_m[s * BATCH + b] - M);
        L   += w[s] * g_l[s * BATCH + b];
    }
    const float inv = 1.0f / L;

    float4 o = make_float4(0.f, 0.f, 0.f, 0.f);
    #pragma unroll
    for (int s = 0; s < NSPLIT; s++) {
        const float4 a = reinterpret_cast<const float4*>(g_acc)
                             [(size_t)(s * BATCH + b) * (EDIM / 4) + t];
        o.x += w[s] * a.x;
        o.y += w[s] * a.y;
        o.z += w[s] * a.z;
        o.w += w[s] * a.w;
    }
    o.x *= inv; o.y *= inv; o.z *= inv; o.w *= inv;
    reinterpret_cast<float4*>(out)[(size_t)b * (EDIM / 4) + t] = o;

    if (t == 0) g_cnt[b] = 0;   // reset for next replay (graph-deterministic)
}

// ---------------------------------------------------------------------------
// Inputs (metadata order): 0=state_tm1 (B,SD)  1=embeddings (N,B,ED)
//                          2=W (SD+ED,1)       3=b (1,)
// state_tm1 / b / W_s are provably irrelevant: the per-b constant state_score
// cancels in softmax over n. Output: (B, ED) float32.
// ---------------------------------------------------------------------------
extern "C" void kernel_launch(void* const* d_in, const int* in_sizes, int n_in,
                              void* d_out, int out_size)
{
    const float* emb = (const float*)d_in[1];
    const float* W   = (const float*)d_in[2];
    float*       out = (float*)d_out;

    dim3 grid(NSPLIT, BATCH);
    attn_fused<<<grid, THREADS>>>(emb, W, out);
}